// round 10
// baseline (speedup 1.0000x reference)
#include <cuda_runtime.h>
#include <cuda_bf16.h>

// Persistent 2-layer tanh RNN, sm_103 baseline tensor cores (mma.sync bf16 x3).
// R9: (1) cross-barrier cp.async prefetch (weights always; activations where
//         already stable) so phase fills hide under dump/barrier/reduce,
//     (2) 144 CTAs (16 tiles x 9 k-splits, 4/4/4/4/4/3/3/3/3 chunks) to use
//         more of the 148+ SMs,
//     (3) __ldcg partial reads in reduces.

typedef unsigned long long u64;
typedef unsigned int u32;

namespace {
constexpr int NCTA = 144;
constexpr int NTHR = 256;
constexpr int Bm = 256, Hd = 1024, Ind = 256, Tt = 512;
constexpr int KS = 9;     // split-K ways
// double-buffered dynamic smem: per buffer 4 bf16 tiles (Ah, Al, Wh, Wl) x 16KB
constexpr int BUFB = 65536;
constexpr int T_AH = 0, T_AL = 16384, T_WH = 32768, T_WL = 49152;
constexpr int SMEM_BYTES = 2 * BUFB;  // 128KB
}

// ---- device-global state (allocation-free rule) ----
__device__ __align__(16) __nv_bfloat16 g_Wih0h[Hd * Ind], g_Wih0l[Hd * Ind];
__device__ __align__(16) __nv_bfloat16 g_Whh0h[Hd * Hd],  g_Whh0l[Hd * Hd];
__device__ __align__(16) __nv_bfloat16 g_Wih1h[Hd * Hd],  g_Wih1l[Hd * Hd];
__device__ __align__(16) __nv_bfloat16 g_Whh1h[Hd * Hd],  g_Whh1l[Hd * Hd];
__device__ __align__(16) __nv_bfloat16 g_M0h[Hd * Hd],    g_M0l[Hd * Hd];
__device__ __align__(16) __nv_bfloat16 g_fcWh[Ind * Hd],  g_fcWl[Ind * Hd];
__device__ __align__(16) __nv_bfloat16 g_fcWTh[Hd * Ind], g_fcWTl[Hd * Ind];
__device__ __align__(16) __nv_bfloat16 g_yh[Bm * Ind],    g_yl[Bm * Ind];
__device__ __align__(16) __nv_bfloat16 g_h0h[Bm * Hd],    g_h0l[Bm * Hd];
// full h1 history (hi/lo) for the batched output GEMM: 512 x 256 x 1024
__device__ __align__(16) __nv_bfloat16 g_H1h[Tt * Bm * Hd];
__device__ __align__(16) __nv_bfloat16 g_H1l[Tt * Bm * Hd];
__device__ float g_biasA1[Hd], g_biasAf[Hd], g_biasB[Hd];
__device__ float g_p[KS][Bm * Hd];    // split-K partials (also M0 scratch in [0..1])
__device__ unsigned g_arrive = 0, g_gen = 0;

// ---- helpers ----
__device__ __forceinline__ u32 smem_u32(const void *p) {
    u32 a;
    asm("{ .reg .u64 t; cvta.to.shared.u64 t, %1; cvt.u32.u64 %0, t; }"
        : "=r"(a) : "l"(p));
    return a;
}

#define LDMX4(r, a) \
    asm volatile("ldmatrix.sync.aligned.m8n8.x4.shared.b16 {%0,%1,%2,%3}, [%4];" \
                 : "=r"((r)[0]), "=r"((r)[1]), "=r"((r)[2]), "=r"((r)[3]) : "r"(a))

__device__ __forceinline__ void mma16816(float *c, const u32 *a, u32 b0, u32 b1) {
    asm volatile(
        "mma.sync.aligned.m16n8k16.row.col.f32.bf16.bf16.f32 "
        "{%0,%1,%2,%3}, {%4,%5,%6,%7}, {%8,%9}, {%0,%1,%2,%3};"
        : "+f"(c[0]), "+f"(c[1]), "+f"(c[2]), "+f"(c[3])
        : "r"(a[0]), "r"(a[1]), "r"(a[2]), "r"(a[3]), "r"(b0), "r"(b1));
}

// ---- grid barrier (validated R4-R8) ----
__device__ __forceinline__ void grid_sync() {
    __syncthreads();
    if (threadIdx.x == 0) {
        unsigned gen = *(volatile unsigned *)&g_gen;
        __threadfence();
        if (atomicAdd(&g_arrive, 1u) == NCTA - 1) {
            atomicExch(&g_arrive, 0u);
            __threadfence();
            atomicAdd(&g_gen, 1u);
        } else {
            while (*(volatile unsigned *)&g_gen == gen) { }
            __threadfence();
        }
    }
    __syncthreads();
}

__device__ __forceinline__ void split_bf16(float v, __nv_bfloat16 &h, __nv_bfloat16 &l) {
    h = __float2bfloat16(v);
    l = __float2bfloat16(v - __bfloat162float(h));
}

// cp.async one 128x64 bf16 tile (SW128 xor swizzle) into smem.
__device__ __forceinline__ void stage_async(u32 sdst, const __nv_bfloat16 *g,
                                            int ld, int kb) {
    const int tid = threadIdx.x;
#pragma unroll
    for (int j = 0; j < 4; ++j) {
        const int u = tid + NTHR * j;
        const int row = u >> 3, blk = u & 7;
        const size_t src = __cvta_generic_to_global(&g[(long)row * ld + kb + blk * 8]);
        const u32 dst = sdst + row * 128 + ((blk ^ (row & 7)) << 4);
        asm volatile("cp.async.cg.shared.global [%0], [%1], 16;"
                     :: "r"(dst), "l"(src) : "memory");
    }
}

// ---- phase descriptor ----
struct Ph {
    const __nv_bfloat16 *Ah, *Al, *Wh, *Wl;
    int lda, ldw, kb, nch;
    bool ready;  // activations stable at pre-issue time
};

__device__ __forceinline__ void commitg() {
    asm volatile("cp.async.commit_group;" ::: "memory");
}
__device__ __forceinline__ void waitg0() {
    asm volatile("cp.async.wait_group 0;" ::: "memory");
}
__device__ __forceinline__ void waitg1() {
    asm volatile("cp.async.wait_group 1;" ::: "memory");
}

// Pre-issue (before dump/barriers/reduce): weights for chunks 0,1 always,
// activations too when already stable. One commit group.
__device__ __forceinline__ void pre_issue(u32 sb, const Ph &p) {
    stage_async(sb + T_WH, p.Wh, p.ldw, p.kb);
    stage_async(sb + T_WL, p.Wl, p.ldw, p.kb);
    if (p.ready) {
        stage_async(sb + T_AH, p.Ah, p.lda, p.kb);
        stage_async(sb + T_AL, p.Al, p.lda, p.kb);
    }
    if (p.nch > 1) {
        stage_async(sb + BUFB + T_WH, p.Wh, p.ldw, p.kb + 64);
        stage_async(sb + BUFB + T_WL, p.Wl, p.ldw, p.kb + 64);
        if (p.ready) {
            stage_async(sb + BUFB + T_AH, p.Ah, p.lda, p.kb + 64);
            stage_async(sb + BUFB + T_AL, p.Al, p.lda, p.kb + 64);
        }
    }
    commitg();
}

// Post-issue (right after the reduce barrier): fresh activations. One commit.
__device__ __forceinline__ void post_issue(u32 sb, const Ph &p) {
    if (!p.ready) {
        stage_async(sb + T_AH, p.Ah, p.lda, p.kb);
        stage_async(sb + T_AL, p.Al, p.lda, p.kb);
        if (p.nch > 1) {
            stage_async(sb + BUFB + T_AH, p.Ah, p.lda, p.kb + 64);
            stage_async(sb + BUFB + T_AL, p.Al, p.lda, p.kb + 64);
        }
    }
    commitg();
}

// MMA over one staged 64-k chunk. 8 warps as 2x4; warp tile 64x32.
// 3 precision passes: ah*bh + ah*bl + al*bh.
__device__ __forceinline__ void mma_tile(float (&acc)[4][4][4], u32 sbase) {
    const int lid = threadIdx.x & 31, wid = threadIdx.x >> 5;
    const int wm = wid >> 2, wn = wid & 3;
    const int rA0 = wm * 64 + (lid & 7) + ((lid >> 3) & 1) * 8;
    const int cAsel = (lid >> 4) & 1;
    const int rB0 = wn * 32 + (lid & 7) + ((lid >> 4) & 1) * 8;
    const int cBsel = (lid >> 3) & 1;
#pragma unroll
    for (int k16 = 0; k16 < 4; ++k16) {
        u32 ah[4][4], al[4][4], bh[2][4], bl[2][4];
#pragma unroll
        for (int ma = 0; ma < 4; ++ma) {
            const int r = rA0 + ma * 16;
            const u32 off = (u32)(r * 128 + (((k16 * 2 + cAsel) ^ (r & 7)) << 4));
            LDMX4(ah[ma], sbase + T_AH + off);
            LDMX4(al[ma], sbase + T_AL + off);
        }
#pragma unroll
        for (int p = 0; p < 2; ++p) {
            const int r = rB0 + p * 16;
            const u32 off = (u32)(r * 128 + (((k16 * 2 + cBsel) ^ (r & 7)) << 4));
            LDMX4(bh[p], sbase + T_WH + off);
            LDMX4(bl[p], sbase + T_WL + off);
        }
#pragma unroll
        for (int ma = 0; ma < 4; ++ma)
#pragma unroll
            for (int na = 0; na < 4; ++na) {
                const int p = na >> 1, q = (na & 1) * 2;
                mma16816(acc[ma][na], ah[ma], bh[p][q], bh[p][q + 1]);
                mma16816(acc[ma][na], ah[ma], bl[p][q], bl[p][q + 1]);
                mma16816(acc[ma][na], al[ma], bh[p][q], bh[p][q + 1]);
            }
    }
}

// Run a phase whose chunks 0,1 were pre/post-issued (2 commit groups pending).
__device__ __forceinline__ void run_phase(float (&acc)[4][4][4], u32 sb, const Ph &p) {
    waitg0();
    __syncthreads();
    for (int i = 0; i < p.nch; ++i) {
        if (i > 0) {
            if (i + 1 < p.nch) waitg1(); else waitg0();
            __syncthreads();
        }
        mma_tile(acc, sb + (u32)((i & 1) * BUFB));
        __syncthreads();
        if (i + 2 < p.nch) {
            const u32 buf = sb + (u32)((i & 1) * BUFB);
            const int kb = p.kb + 64 * (i + 2);
            stage_async(buf + T_AH, p.Ah, p.lda, kb);
            stage_async(buf + T_AL, p.Al, p.lda, kb);
            stage_async(buf + T_WH, p.Wh, p.ldw, kb);
            stage_async(buf + T_WL, p.Wl, p.ldw, kb);
            commitg();
        }
    }
}

// Self-contained pipelined GEMM (phase0b + final GEMM paths).
__device__ __forceinline__ void issue_chunk(
    u32 sbuf, const __nv_bfloat16 *Ah, const __nv_bfloat16 *Al, int lda,
    const __nv_bfloat16 *Wh, const __nv_bfloat16 *Wl, int ldw, int kb) {
    stage_async(sbuf + T_AH, Ah, lda, kb);
    stage_async(sbuf + T_AL, Al, lda, kb);
    stage_async(sbuf + T_WH, Wh, ldw, kb);
    stage_async(sbuf + T_WL, Wl, ldw, kb);
    commitg();
}

__device__ __forceinline__ void gemm_pipe(
    float (&acc)[4][4][4], u32 sb,
    const __nv_bfloat16 *Ah, const __nv_bfloat16 *Al, int lda,
    const __nv_bfloat16 *Wh, const __nv_bfloat16 *Wl, int ldw,
    int kb, int nch)
{
    issue_chunk(sb, Ah, Al, lda, Wh, Wl, ldw, kb);
    if (nch > 1) issue_chunk(sb + BUFB, Ah, Al, lda, Wh, Wl, ldw, kb + 64);
    for (int i = 0; i < nch; ++i) {
        if (i + 1 < nch) waitg1(); else waitg0();
        __syncthreads();
        mma_tile(acc, sb + (u32)((i & 1) * BUFB));
        __syncthreads();
        if (i + 2 < nch)
            issue_chunk(sb + (u32)((i & 1) * BUFB), Ah, Al, lda, Wh, Wl, ldw,
                        kb + 64 * (i + 2));
    }
}

// Dump 128x128 fp32 accumulator tile to a partial buffer.
__device__ __forceinline__ void dump_acc(
    const float (&acc)[4][4][4], float *__restrict__ dst, int ldc, int m0, int n0)
{
    const int lid = threadIdx.x & 31, wid = threadIdx.x >> 5;
    const int wm = wid >> 2, wn = wid & 3;
    const int g = lid >> 2, t = lid & 3;
#pragma unroll
    for (int ma = 0; ma < 4; ++ma)
#pragma unroll
        for (int na = 0; na < 4; ++na) {
            const int row = m0 + wm * 64 + ma * 16 + g;
            const int col = n0 + wn * 32 + na * 8 + t * 2;
            *reinterpret_cast<float2 *>(&dst[(long)row * ldc + col]) =
                make_float2(acc[ma][na][0], acc[ma][na][1]);
            *reinterpret_cast<float2 *>(&dst[(long)(row + 8) * ldc + col]) =
                make_float2(acc[ma][na][2], acc[ma][na][3]);
        }
}

// sum cnt split-K partials + bias, tanh, write bf16 hi/lo activations
__device__ __forceinline__ void reduce_stage(
    int cnt, const float *__restrict__ bias,
    __nv_bfloat16 *__restrict__ dh, __nv_bfloat16 *__restrict__ dl, int gtid)
{
    const int base = gtid * 8;
    if (base >= Bm * Hd) return;
#pragma unroll
    for (int q = 0; q < 2; ++q) {
        const int i = base + 4 * q;
        const int n = i & (Hd - 1);
        float4 a = __ldcg(reinterpret_cast<const float4 *>(&g_p[0][i]));
        for (int p = 1; p < cnt; ++p) {
            const float4 t = __ldcg(reinterpret_cast<const float4 *>(&g_p[p][i]));
            a.x += t.x; a.y += t.y; a.z += t.z; a.w += t.w;
        }
        const float4 vb = *reinterpret_cast<const float4 *>(&bias[n]);
        const float ox = tanhf(a.x + vb.x), oy = tanhf(a.y + vb.y);
        const float oz = tanhf(a.z + vb.z), ow = tanhf(a.w + vb.w);
        __nv_bfloat16 hx, lx, hy, ly, hz, lz, hw, lw;
        split_bf16(ox, hx, lx); split_bf16(oy, hy, ly);
        split_bf16(oz, hz, lz); split_bf16(ow, hw, lw);
        reinterpret_cast<__nv_bfloat162 *>(&dh[i])[0] = __halves2bfloat162(hx, hy);
        reinterpret_cast<__nv_bfloat162 *>(&dh[i])[1] = __halves2bfloat162(hz, hw);
        reinterpret_cast<__nv_bfloat162 *>(&dl[i])[0] = __halves2bfloat162(lx, ly);
        reinterpret_cast<__nv_bfloat162 *>(&dl[i])[1] = __halves2bfloat162(lz, lw);
    }
}

__device__ __forceinline__ void convert_split(
    const float *__restrict__ s, __nv_bfloat16 *dh, __nv_bfloat16 *dl, int n, int gtid)
{
    for (int i = gtid; i < n; i += NCTA * NTHR) split_bf16(s[i], dh[i], dl[i]);
}

// Final-GEMM epilogue: out[:, s, :] tile = acc + fc_b
__device__ __forceinline__ void final_store(
    const float (&acc)[4][4][4], float *__restrict__ out,
    const float *__restrict__ fc_b, int s, int m0, int n0)
{
    const int lid = threadIdx.x & 31, wid = threadIdx.x >> 5;
    const int wm = wid >> 2, wn = wid & 3;
    const int g = lid >> 2, t = lid & 3;
#pragma unroll
    for (int ma = 0; ma < 4; ++ma)
#pragma unroll
        for (int na = 0; na < 4; ++na) {
            const int row = m0 + wm * 64 + ma * 16 + g;
            const int col = n0 + wn * 32 + na * 8 + t * 2;
            const float bx = fc_b[col], by = fc_b[col + 1];
            *reinterpret_cast<float2 *>(
                &out[(long)row * (Tt * Ind) + (long)s * Ind + col]) =
                make_float2(acc[ma][na][0] + bx, acc[ma][na][1] + by);
            *reinterpret_cast<float2 *>(
                &out[(long)(row + 8) * (Tt * Ind) + (long)s * Ind + col]) =
                make_float2(acc[ma][na][2] + bx, acc[ma][na][3] + by);
        }
}

// ks -> (kb, nch) within a 1024-k weight matrix for ks>=4 (5-way: 4,3,3,3 chunks)
__device__ __forceinline__ void ks_hi(int ks, int &kb, int &nch) {
    if (ks == 4) { kb = 0; nch = 4; }
    else { kb = 256 + (ks - 5) * 192; nch = 3; }
}

__global__ void __launch_bounds__(NTHR, 1) rnn_tc(
    const float *__restrict__ y0,
    const float *__restrict__ W_ih0, const float *__restrict__ W_hh0,
    const float *__restrict__ b_ih0, const float *__restrict__ b_hh0,
    const float *__restrict__ W_ih1, const float *__restrict__ W_hh1,
    const float *__restrict__ b_ih1, const float *__restrict__ b_hh1,
    const float *__restrict__ fc_W, const float *__restrict__ fc_b,
    float *__restrict__ out)
{
    extern __shared__ char smem[];
    const u32 sb = smem_u32(smem);
    const int tid = threadIdx.x, bid = blockIdx.x;
    const int gtid = bid * NTHR + tid;
    const int stride = NCTA * NTHR;

    // ---- phase 0a (every replay): splits, transpose, init, biases
    convert_split(W_ih0, g_Wih0h, g_Wih0l, Hd * Ind, gtid);
    convert_split(W_hh0, g_Whh0h, g_Whh0l, Hd * Hd, gtid);
    convert_split(W_ih1, g_Wih1h, g_Wih1l, Hd * Hd, gtid);
    convert_split(W_hh1, g_Whh1h, g_Whh1l, Hd * Hd, gtid);
    convert_split(fc_W, g_fcWh, g_fcWl, Ind * Hd, gtid);
    for (int i = gtid; i < Hd * Ind; i += stride) {  // fcWT[j][k] = fc_W[k][j]
        const int j = i >> 8, k = i & 255;
        split_bf16(fc_W[(long)k * Hd + j], g_fcWTh[i], g_fcWTl[i]);
    }
    for (int i = gtid; i < Bm * Ind; i += stride) {
        const float v = y0[i];
        split_bf16(v, g_yh[i], g_yl[i]);
        out[(long)(i >> 8) * (Tt * Ind) + (i & 255)] = v;  // out[:, 0, :]
    }
    for (int i = gtid; i < Bm * Hd; i += stride) {
        const __nv_bfloat16 z = __float2bfloat16(0.0f);
        g_h0h[i] = z; g_h0l[i] = z;
        g_H1h[i] = z; g_H1l[i] = z;   // history slot 0 = h1 initial state
    }
    for (int j = gtid; j < Hd; j += stride) {
        const float s1 = b_ih0[j] + b_hh0[j];
        g_biasA1[j] = s1;
        float a = 0.0f;
        const float *wr = &W_ih0[(long)j * Ind];
        for (int k = 0; k < Ind; ++k) a += wr[k] * fc_b[k];
        g_biasAf[j] = a + s1;              // (fc_b @ W_ih0^T + b_ih0 + b_hh0)
        g_biasB[j] = b_ih1[j] + b_hh1[j];
    }
    grid_sync();

    // ---- phase 0b: M0 = W_ih0 @ fc_W  (1024x1024, K=256), 64 tiles x 2 k-splits
    if (bid < 128) {
        const int ks = bid >> 6, tj = bid & 63, tm = tj >> 3, tn = tj & 7;
        float acc[4][4][4] = {};
        gemm_pipe(acc, sb,
                  g_Wih0h + (long)tm * 128 * Ind, g_Wih0l + (long)tm * 128 * Ind, Ind,
                  g_fcWTh + (long)tn * 128 * Ind, g_fcWTl + (long)tn * 128 * Ind, Ind,
                  ks * 128, 2);
        dump_acc(acc, &g_p[0][0] + (long)ks * Hd * Hd, Hd, tm * 128, tn * 128);
    }
    grid_sync();
    {   // M0 reduce + split to bf16 hi/lo
        const float *p0 = &g_p[0][0];
        const float *p1 = p0 + (long)Hd * Hd;
        for (int i = gtid * 4; i < Hd * Hd; i += stride * 4) {
            const float4 a = __ldcg(reinterpret_cast<const float4 *>(&p0[i]));
            const float4 b = __ldcg(reinterpret_cast<const float4 *>(&p1[i]));
            split_bf16(a.x + b.x, g_M0h[i], g_M0l[i]);
            split_bf16(a.y + b.y, g_M0h[i + 1], g_M0l[i + 1]);
            split_bf16(a.z + b.z, g_M0h[i + 2], g_M0l[i + 2]);
            split_bf16(a.w + b.w, g_M0h[i + 3], g_M0l[i + 3]);
        }
    }
    grid_sync();

    // tile mapping: 9 k-splits x (2m x 8n) over [256, 1024]
    const int ksAB = bid >> 4;
    const int m0AB = ((bid >> 3) & 1) * 128, n0AB = (bid & 7) * 128;

    // phase makers
    auto makeA = [&](int s) {
        Ph p; p.nch = 0;
        if (s == 1) {
            if (ksAB < 4) {
                p.Ah = g_yh + (long)m0AB * Ind; p.Al = g_yl + (long)m0AB * Ind;
                p.Wh = g_Wih0h + (long)n0AB * Ind; p.Wl = g_Wih0l + (long)n0AB * Ind;
                p.lda = Ind; p.ldw = Ind; p.kb = ksAB * 64; p.nch = 1; p.ready = true;
            }
        } else if (ksAB < 4) {
            const long hb = (long)(s - 1) * Bm * Hd + (long)m0AB * Hd;
            p.Ah = g_H1h + hb; p.Al = g_H1l + hb;
            p.Wh = g_M0h + (long)n0AB * Hd; p.Wl = g_M0l + (long)n0AB * Hd;
            p.lda = Hd; p.ldw = Hd; p.kb = ksAB * 256; p.nch = 4; p.ready = false;
        } else {
            p.Ah = g_h0h + (long)m0AB * Hd; p.Al = g_h0l + (long)m0AB * Hd;
            p.Wh = g_Whh0h + (long)n0AB * Hd; p.Wl = g_Whh0l + (long)n0AB * Hd;
            p.lda = Hd; p.ldw = Hd; ks_hi(ksAB, p.kb, p.nch); p.ready = true;
        }
        return p;
    };
    auto makeB = [&](int s) {
        Ph p;
        if (ksAB < 4) {
            p.Ah = g_h0h + (long)m0AB * Hd; p.Al = g_h0l + (long)m0AB * Hd;
            p.Wh = g_Wih1h + (long)n0AB * Hd; p.Wl = g_Wih1l + (long)n0AB * Hd;
            p.lda = Hd; p.ldw = Hd; p.kb = ksAB * 256; p.nch = 4; p.ready = false;
        } else {
            const long hb = (long)(s - 1) * Bm * Hd + (long)m0AB * Hd;
            p.Ah = g_H1h + hb; p.Al = g_H1l + hb;
            p.Wh = g_Whh1h + (long)n0AB * Hd; p.Wl = g_Whh1l + (long)n0AB * Hd;
            p.lda = Hd; p.ldw = Hd; ks_hi(ksAB, p.kb, p.nch); p.ready = true;
        }
        return p;
    };

    Ph pA = makeA(1);
    if (pA.nch > 0) pre_issue(sb, pA);

    for (int s = 1; s < Tt; ++s) {
        float accA[4][4][4] = {};
        // ---- stage A: h0new = tanh([h1prev|h0] @ [M0|Whh0]^T + biasAf)
        if (pA.nch > 0) {
            post_issue(sb, pA);
            run_phase(accA, sb, pA);
        }
        Ph pB = makeB(s);
        pre_issue(sb, pB);              // W always; A too for ks>=4 (h1prev stable)
        if (pA.nch > 0) dump_acc(accA, g_p[ksAB], Hd, m0AB, n0AB);
        grid_sync();
        reduce_stage(s == 1 ? 4 : KS, s == 1 ? g_biasA1 : g_biasAf,
                     g_h0h, g_h0l, gtid);
        grid_sync();

        // ---- stage B: h1(s) = tanh([h0new|h1prev] @ [Wih1|Whh1]^T + biasB)
        post_issue(sb, pB);             // fresh h0new for ks<4
        float accB[4][4][4] = {};
        run_phase(accB, sb, pB);
        Ph pAn; pAn.nch = 0;
        if (s + 1 < Tt) {
            pAn = makeA(s + 1);
            if (pAn.nch > 0) pre_issue(sb, pAn);  // W always; A for ks>=4 (h0 stable)
        }
        dump_acc(accB, g_p[ksAB], Hd, m0AB, n0AB);
        grid_sync();
        reduce_stage(KS, g_biasB,
                     g_H1h + (long)s * Bm * Hd, g_H1l + (long)s * Bm * Hd, gtid);
        grid_sync();
        pA = pAn;
    }

    // ---- batched output GEMM: out[:, s, :] = H1[s] @ fc_W^T + fc_b, s = 1..511
    for (int job = bid; job < (Tt - 1) * 4; job += NCTA) {
        const int ntile = job & 1;
        const int rt = job >> 1;
        const int s = 1 + (rt >> 1);
        const int m0 = (rt & 1) * 128, n0 = ntile * 128;
        float acc[4][4][4] = {};
        gemm_pipe(acc, sb,
                  g_H1h + (long)s * Bm * Hd + (long)m0 * Hd,
                  g_H1l + (long)s * Bm * Hd + (long)m0 * Hd, Hd,
                  g_fcWh + (long)n0 * Hd, g_fcWl + (long)n0 * Hd, Hd,
                  0, 16);
        final_store(acc, out, fc_b, s, m0, n0);
    }
}

extern "C" void kernel_launch(void *const *d_in, const int *in_sizes, int n_in,
                              void *d_out, int out_size) {
    (void)in_sizes; (void)n_in; (void)out_size;
    const float *y0    = (const float *)d_in[0];
    // d_in[1] = t (length only; unused)
    const float *W_ih0 = (const float *)d_in[2];
    const float *W_hh0 = (const float *)d_in[3];
    const float *b_ih0 = (const float *)d_in[4];
    const float *b_hh0 = (const float *)d_in[5];
    const float *W_ih1 = (const float *)d_in[6];
    const float *W_hh1 = (const float *)d_in[7];
    const float *b_ih1 = (const float *)d_in[8];
    const float *b_hh1 = (const float *)d_in[9];
    const float *fc_W  = (const float *)d_in[10];
    const float *fc_b  = (const float *)d_in[11];
    float *out = (float *)d_out;

    cudaFuncSetAttribute(rnn_tc, cudaFuncAttributeMaxDynamicSharedMemorySize, SMEM_BYTES);
    rnn_tc<<<NCTA, NTHR, SMEM_BYTES>>>(y0, W_ih0, W_hh0, b_ih0, b_hh0,
                                       W_ih1, W_hh1, b_ih1, b_hh1,
                                       fc_W, fc_b, out);
}

// round 11
// speedup vs baseline: 1.5239x; 1.5239x over previous
#include <cuda_runtime.h>
#include <cuda_bf16.h>

// Persistent 2-layer tanh RNN, sm_103 baseline tensor cores (mma.sync bf16 x3).
// R10 = R8 (proven 15.5ms config: 128 CTAs, 8-way split-K, fc folded via M0,
// batched output GEMM) + ONE change: chunk-0 prefetch into a dedicated smem
// region P across the dump/barrier/reduce window. R9's 144-CTA/9-split
// restructure regressed and is reverted.

typedef unsigned long long u64;
typedef unsigned int u32;

namespace {
constexpr int NCTA = 128;
constexpr int NTHR = 256;
constexpr int Bm = 256, Hd = 1024, Ind = 256, Tt = 512;
// smem: ring buffers buf0, buf1 + prefetch region P. Each 64KB = 4 bf16 tiles.
constexpr int BUFB = 65536;
constexpr int T_AH = 0, T_AL = 16384, T_WH = 32768, T_WL = 49152;
constexpr int SMEM_BYTES = 3 * BUFB;  // 192KB
}

// ---- device-global state (allocation-free rule) ----
__device__ __align__(16) __nv_bfloat16 g_Wih0h[Hd * Ind], g_Wih0l[Hd * Ind];
__device__ __align__(16) __nv_bfloat16 g_Whh0h[Hd * Hd],  g_Whh0l[Hd * Hd];
__device__ __align__(16) __nv_bfloat16 g_Wih1h[Hd * Hd],  g_Wih1l[Hd * Hd];
__device__ __align__(16) __nv_bfloat16 g_Whh1h[Hd * Hd],  g_Whh1l[Hd * Hd];
__device__ __align__(16) __nv_bfloat16 g_M0h[Hd * Hd],    g_M0l[Hd * Hd];
__device__ __align__(16) __nv_bfloat16 g_fcWh[Ind * Hd],  g_fcWl[Ind * Hd];
__device__ __align__(16) __nv_bfloat16 g_fcWTh[Hd * Ind], g_fcWTl[Hd * Ind];
__device__ __align__(16) __nv_bfloat16 g_yh[Bm * Ind],    g_yl[Bm * Ind];
__device__ __align__(16) __nv_bfloat16 g_h0h[2][Bm * Hd], g_h0l[2][Bm * Hd];
// full h1 history (hi/lo) for the batched output GEMM: 512 x 256 x 1024
__device__ __align__(16) __nv_bfloat16 g_H1h[Tt * Bm * Hd];
__device__ __align__(16) __nv_bfloat16 g_H1l[Tt * Bm * Hd];
__device__ float g_biasA1[Hd], g_biasAf[Hd], g_biasB[Hd];
__device__ float g_pAB[8][Bm * Hd];   // split-K partials (also M0 scratch: 2 x 1M)
__device__ unsigned g_arrive = 0, g_gen = 0;

// ---- helpers ----
__device__ __forceinline__ u32 smem_u32(const void *p) {
    u32 a;
    asm("{ .reg .u64 t; cvta.to.shared.u64 t, %1; cvt.u32.u64 %0, t; }"
        : "=r"(a) : "l"(p));
    return a;
}

#define LDMX4(r, a) \
    asm volatile("ldmatrix.sync.aligned.m8n8.x4.shared.b16 {%0,%1,%2,%3}, [%4];" \
                 : "=r"((r)[0]), "=r"((r)[1]), "=r"((r)[2]), "=r"((r)[3]) : "r"(a))

__device__ __forceinline__ void mma16816(float *c, const u32 *a, u32 b0, u32 b1) {
    asm volatile(
        "mma.sync.aligned.m16n8k16.row.col.f32.bf16.bf16.f32 "
        "{%0,%1,%2,%3}, {%4,%5,%6,%7}, {%8,%9}, {%0,%1,%2,%3};"
        : "+f"(c[0]), "+f"(c[1]), "+f"(c[2]), "+f"(c[3])
        : "r"(a[0]), "r"(a[1]), "r"(a[2]), "r"(a[3]), "r"(b0), "r"(b1));
}

__device__ __forceinline__ void commitg() {
    asm volatile("cp.async.commit_group;" ::: "memory");
}
__device__ __forceinline__ void waitg0() {
    asm volatile("cp.async.wait_group 0;" ::: "memory");
}
__device__ __forceinline__ void waitg1() {
    asm volatile("cp.async.wait_group 1;" ::: "memory");
}
__device__ __forceinline__ void waitg2() {
    asm volatile("cp.async.wait_group 2;" ::: "memory");
}

// ---- grid barrier (validated R4-R9) ----
__device__ __forceinline__ void grid_sync() {
    __syncthreads();
    if (threadIdx.x == 0) {
        unsigned gen = *(volatile unsigned *)&g_gen;
        __threadfence();
        if (atomicAdd(&g_arrive, 1u) == NCTA - 1) {
            atomicExch(&g_arrive, 0u);
            __threadfence();
            atomicAdd(&g_gen, 1u);
        } else {
            while (*(volatile unsigned *)&g_gen == gen) { }
            __threadfence();
        }
    }
    __syncthreads();
}

__device__ __forceinline__ void split_bf16(float v, __nv_bfloat16 &h, __nv_bfloat16 &l) {
    h = __float2bfloat16(v);
    l = __float2bfloat16(v - __bfloat162float(h));
}

// cp.async one 128x64 bf16 tile (SW128 xor swizzle) into smem.
__device__ __forceinline__ void stage_async(u32 sdst, const __nv_bfloat16 *g,
                                            int ld, int kb) {
    const int tid = threadIdx.x;
#pragma unroll
    for (int j = 0; j < 4; ++j) {
        const int u = tid + NTHR * j;
        const int row = u >> 3, blk = u & 7;
        const size_t src = __cvta_generic_to_global(&g[(long)row * ld + kb + blk * 8]);
        const u32 dst = sdst + row * 128 + ((blk ^ (row & 7)) << 4);
        asm volatile("cp.async.cg.shared.global [%0], [%1], 16;"
                     :: "r"(dst), "l"(src) : "memory");
    }
}

__device__ __forceinline__ void issue_chunk(
    u32 sbuf, const __nv_bfloat16 *Ah, const __nv_bfloat16 *Al, int lda,
    const __nv_bfloat16 *Wh, const __nv_bfloat16 *Wl, int ldw, int kb) {
    stage_async(sbuf + T_AH, Ah, lda, kb);
    stage_async(sbuf + T_AL, Al, lda, kb);
    stage_async(sbuf + T_WH, Wh, ldw, kb);
    stage_async(sbuf + T_WL, Wl, ldw, kb);
    commitg();
}

// ---- phase descriptor ----
struct Ph {
    const __nv_bfloat16 *Ah, *Al, *Wh, *Wl;
    int lda, ldw, kb, nch;
    bool ready;  // activations stable at prefetch time
};

// Prefetch chunk 0 into P (weights always; activations when stable).
// Issued after the phase's dump, before the barriers; completes during them.
__device__ __forceinline__ void prefetch_phase(u32 sb, const Ph &p) {
    const u32 P = sb + 2 * BUFB;
    stage_async(P + T_WH, p.Wh, p.ldw, p.kb);
    stage_async(P + T_WL, p.Wl, p.ldw, p.kb);
    if (p.ready) {
        stage_async(P + T_AH, p.Ah, p.lda, p.kb);
        stage_async(P + T_AL, p.Al, p.lda, p.kb);
    }
    commitg();
}

// Phase start (after the reduce barrier): fresh chunk-0 activations if needed,
// then chunks 1 and 2 into the ring buffers.
__device__ __forceinline__ void start_phase(u32 sb, const Ph &p) {
    const u32 P = sb + 2 * BUFB;
    if (!p.ready) {
        stage_async(P + T_AH, p.Ah, p.lda, p.kb);
        stage_async(P + T_AL, p.Al, p.lda, p.kb);
    }
    commitg();
    if (p.nch > 1)
        issue_chunk(sb, p.Ah, p.Al, p.lda, p.Wh, p.Wl, p.ldw, p.kb + 64);
    if (p.nch > 2)
        issue_chunk(sb + BUFB, p.Ah, p.Al, p.lda, p.Wh, p.Wl, p.ldw, p.kb + 128);
}

// MMA over one staged 64-k chunk. 8 warps as 2x4; warp tile 64x32.
// 3 precision passes: ah*bh + ah*bl + al*bh.
__device__ __forceinline__ void mma_tile(float (&acc)[4][4][4], u32 sbase) {
    const int lid = threadIdx.x & 31, wid = threadIdx.x >> 5;
    const int wm = wid >> 2, wn = wid & 3;
    const int rA0 = wm * 64 + (lid & 7) + ((lid >> 3) & 1) * 8;
    const int cAsel = (lid >> 4) & 1;
    const int rB0 = wn * 32 + (lid & 7) + ((lid >> 4) & 1) * 8;
    const int cBsel = (lid >> 3) & 1;
#pragma unroll
    for (int k16 = 0; k16 < 4; ++k16) {
        u32 ah[4][4], al[4][4], bh[2][4], bl[2][4];
#pragma unroll
        for (int ma = 0; ma < 4; ++ma) {
            const int r = rA0 + ma * 16;
            const u32 off = (u32)(r * 128 + (((k16 * 2 + cAsel) ^ (r & 7)) << 4));
            LDMX4(ah[ma], sbase + T_AH + off);
            LDMX4(al[ma], sbase + T_AL + off);
        }
#pragma unroll
        for (int p = 0; p < 2; ++p) {
            const int r = rB0 + p * 16;
            const u32 off = (u32)(r * 128 + (((k16 * 2 + cBsel) ^ (r & 7)) << 4));
            LDMX4(bh[p], sbase + T_WH + off);
            LDMX4(bl[p], sbase + T_WL + off);
        }
#pragma unroll
        for (int ma = 0; ma < 4; ++ma)
#pragma unroll
            for (int na = 0; na < 4; ++na) {
                const int p = na >> 1, q = (na & 1) * 2;
                mma16816(acc[ma][na], ah[ma], bh[p][q], bh[p][q + 1]);
                mma16816(acc[ma][na], ah[ma], bl[p][q], bl[p][q + 1]);
                mma16816(acc[ma][na], al[ma], bh[p][q], bh[p][q + 1]);
            }
    }
}

// Run a prefetched+started phase. Chunk 0 lives in P; chunk j>=1 in buf((j-1)&1).
// Pending groups at entry: [G_pre][G_s0][c1][c2] (FIFO).
__device__ __forceinline__ void run_phase(float (&acc)[4][4][4], u32 sb, const Ph &p) {
    const u32 P = sb + 2 * BUFB;
    for (int i = 0; i < p.nch; ++i) {
        if (i == 0) {
            if (p.nch >= 3) waitg2();
            else if (p.nch == 2) waitg1();
            else waitg0();
        } else if (i + 1 < p.nch) {
            waitg1();
        } else {
            waitg0();
        }
        __syncthreads();
        mma_tile(acc, i == 0 ? P : sb + (u32)(((i - 1) & 1) * BUFB));
        __syncthreads();
        if (i >= 1 && i + 2 < p.nch)
            issue_chunk(sb + (u32)(((i + 1) & 1) * BUFB),
                        p.Ah, p.Al, p.lda, p.Wh, p.Wl, p.ldw, p.kb + 64 * (i + 2));
    }
}

// Self-contained pipelined GEMM (phase0b + final output GEMM), R8 verbatim.
__device__ __forceinline__ void gemm_pipe(
    float (&acc)[4][4][4], u32 sb,
    const __nv_bfloat16 *Ah, const __nv_bfloat16 *Al, int lda,
    const __nv_bfloat16 *Wh, const __nv_bfloat16 *Wl, int ldw,
    int kb, int nch)
{
    issue_chunk(sb, Ah, Al, lda, Wh, Wl, ldw, kb);
    if (nch > 1) issue_chunk(sb + BUFB, Ah, Al, lda, Wh, Wl, ldw, kb + 64);
    for (int i = 0; i < nch; ++i) {
        if (i + 1 < nch) waitg1(); else waitg0();
        __syncthreads();
        mma_tile(acc, sb + (u32)((i & 1) * BUFB));
        __syncthreads();
        if (i + 2 < nch)
            issue_chunk(sb + (u32)((i & 1) * BUFB), Ah, Al, lda, Wh, Wl, ldw,
                        kb + 64 * (i + 2));
    }
}

// Dump 128x128 fp32 accumulator tile to a partial buffer.
__device__ __forceinline__ void dump_acc(
    const float (&acc)[4][4][4], float *__restrict__ dst, int ldc, int m0, int n0)
{
    const int lid = threadIdx.x & 31, wid = threadIdx.x >> 5;
    const int wm = wid >> 2, wn = wid & 3;
    const int g = lid >> 2, t = lid & 3;
#pragma unroll
    for (int ma = 0; ma < 4; ++ma)
#pragma unroll
        for (int na = 0; na < 4; ++na) {
            const int row = m0 + wm * 64 + ma * 16 + g;
            const int col = n0 + wn * 32 + na * 8 + t * 2;
            *reinterpret_cast<float2 *>(&dst[(long)row * ldc + col]) =
                make_float2(acc[ma][na][0], acc[ma][na][1]);
            *reinterpret_cast<float2 *>(&dst[(long)(row + 8) * ldc + col]) =
                make_float2(acc[ma][na][2], acc[ma][na][3]);
        }
}

// sum 8 split-K partials + bias, tanh, write bf16 hi/lo activations
__device__ __forceinline__ void reduce_stage(
    const float *__restrict__ bias,
    __nv_bfloat16 *__restrict__ dh, __nv_bfloat16 *__restrict__ dl, int gtid)
{
    const int base = gtid * 8;
#pragma unroll
    for (int q = 0; q < 2; ++q) {
        const int i = base + 4 * q;
        const int n = i & (Hd - 1);
        float4 a = __ldcg(reinterpret_cast<const float4 *>(&g_pAB[0][i]));
#pragma unroll
        for (int p = 1; p < 8; ++p) {
            const float4 t = __ldcg(reinterpret_cast<const float4 *>(&g_pAB[p][i]));
            a.x += t.x; a.y += t.y; a.z += t.z; a.w += t.w;
        }
        const float4 vb = *reinterpret_cast<const float4 *>(&bias[n]);
        const float ox = tanhf(a.x + vb.x), oy = tanhf(a.y + vb.y);
        const float oz = tanhf(a.z + vb.z), ow = tanhf(a.w + vb.w);
        __nv_bfloat16 hx, lx, hy, ly, hz, lz, hw, lw;
        split_bf16(ox, hx, lx); split_bf16(oy, hy, ly);
        split_bf16(oz, hz, lz); split_bf16(ow, hw, lw);
        reinterpret_cast<__nv_bfloat162 *>(&dh[i])[0] = __halves2bfloat162(hx, hy);
        reinterpret_cast<__nv_bfloat162 *>(&dh[i])[1] = __halves2bfloat162(hz, hw);
        reinterpret_cast<__nv_bfloat162 *>(&dl[i])[0] = __halves2bfloat162(lx, ly);
        reinterpret_cast<__nv_bfloat162 *>(&dl[i])[1] = __halves2bfloat162(lz, lw);
    }
}

__device__ __forceinline__ void convert_split(
    const float *__restrict__ s, __nv_bfloat16 *dh, __nv_bfloat16 *dl, int n, int gtid)
{
    for (int i = gtid; i < n; i += NCTA * NTHR) split_bf16(s[i], dh[i], dl[i]);
}

// Final-GEMM epilogue: out[:, s, :] tile = acc + fc_b
__device__ __forceinline__ void final_store(
    const float (&acc)[4][4][4], float *__restrict__ out,
    const float *__restrict__ fc_b, int s, int m0, int n0)
{
    const int lid = threadIdx.x & 31, wid = threadIdx.x >> 5;
    const int wm = wid >> 2, wn = wid & 3;
    const int g = lid >> 2, t = lid & 3;
#pragma unroll
    for (int ma = 0; ma < 4; ++ma)
#pragma unroll
        for (int na = 0; na < 4; ++na) {
            const int row = m0 + wm * 64 + ma * 16 + g;
            const int col = n0 + wn * 32 + na * 8 + t * 2;
            const float bx = fc_b[col], by = fc_b[col + 1];
            *reinterpret_cast<float2 *>(
                &out[(long)row * (Tt * Ind) + (long)s * Ind + col]) =
                make_float2(acc[ma][na][0] + bx, acc[ma][na][1] + by);
            *reinterpret_cast<float2 *>(
                &out[(long)(row + 8) * (Tt * Ind) + (long)s * Ind + col]) =
                make_float2(acc[ma][na][2] + bx, acc[ma][na][3] + by);
        }
}

__global__ void __launch_bounds__(NTHR, 1) rnn_tc(
    const float *__restrict__ y0,
    const float *__restrict__ W_ih0, const float *__restrict__ W_hh0,
    const float *__restrict__ b_ih0, const float *__restrict__ b_hh0,
    const float *__restrict__ W_ih1, const float *__restrict__ W_hh1,
    const float *__restrict__ b_ih1, const float *__restrict__ b_hh1,
    const float *__restrict__ fc_W, const float *__restrict__ fc_b,
    float *__restrict__ out)
{
    extern __shared__ char smem[];
    const u32 sb = smem_u32(smem);
    const int tid = threadIdx.x, bid = blockIdx.x;
    const int gtid = bid * NTHR + tid;
    const int stride = NCTA * NTHR;

    // ---- phase 0a (every replay): splits, transpose, init, biases
    convert_split(W_ih0, g_Wih0h, g_Wih0l, Hd * Ind, gtid);
    convert_split(W_hh0, g_Whh0h, g_Whh0l, Hd * Hd, gtid);
    convert_split(W_ih1, g_Wih1h, g_Wih1l, Hd * Hd, gtid);
    convert_split(W_hh1, g_Whh1h, g_Whh1l, Hd * Hd, gtid);
    convert_split(fc_W, g_fcWh, g_fcWl, Ind * Hd, gtid);
    for (int i = gtid; i < Hd * Ind; i += stride) {  // fcWT[j][k] = fc_W[k][j]
        const int j = i >> 8, k = i & 255;
        split_bf16(fc_W[(long)k * Hd + j], g_fcWTh[i], g_fcWTl[i]);
    }
    for (int i = gtid; i < Bm * Ind; i += stride) {
        const float v = y0[i];
        split_bf16(v, g_yh[i], g_yl[i]);
        out[(long)(i >> 8) * (Tt * Ind) + (i & 255)] = v;  // out[:, 0, :]
    }
    for (int i = gtid; i < Bm * Hd; i += stride) {
        const __nv_bfloat16 z = __float2bfloat16(0.0f);
        g_h0h[0][i] = z; g_h0l[0][i] = z;
        g_H1h[i] = z;    g_H1l[i] = z;   // history slot 0 = h1 initial state
    }
    for (int j = gtid; j < Hd; j += stride) {
        const float s1 = b_ih0[j] + b_hh0[j];
        g_biasA1[j] = s1;
        float a = 0.0f;
        const float *wr = &W_ih0[(long)j * Ind];
        for (int k = 0; k < Ind; ++k) a += wr[k] * fc_b[k];
        g_biasAf[j] = a + s1;              // (fc_b @ W_ih0^T + b_ih0 + b_hh0)
        g_biasB[j] = b_ih1[j] + b_hh1[j];
    }
    grid_sync();

    // ---- phase 0b: M0 = W_ih0 @ fc_W  (1024x1024, K=256), 64 tiles x 2 k-splits
    {
        const int ks = bid >> 6, tj = bid & 63, tm = tj >> 3, tn = tj & 7;
        float acc[4][4][4] = {};
        gemm_pipe(acc, sb,
                  g_Wih0h + (long)tm * 128 * Ind, g_Wih0l + (long)tm * 128 * Ind, Ind,
                  g_fcWTh + (long)tn * 128 * Ind, g_fcWTl + (long)tn * 128 * Ind, Ind,
                  ks * 128, 2);
        dump_acc(acc, &g_pAB[0][0] + (long)ks * Hd * Hd, Hd, tm * 128, tn * 128);
    }
    grid_sync();
    {   // M0 reduce + split to bf16 hi/lo
        const float *p0 = &g_pAB[0][0];
        const float *p1 = p0 + (long)Hd * Hd;
        for (int i = gtid * 4; i < Hd * Hd; i += stride * 4) {
            const float4 a = __ldcg(reinterpret_cast<const float4 *>(&p0[i]));
            const float4 b = __ldcg(reinterpret_cast<const float4 *>(&p1[i]));
            split_bf16(a.x + b.x, g_M0h[i], g_M0l[i]);
            split_bf16(a.y + b.y, g_M0h[i + 1], g_M0l[i + 1]);
            split_bf16(a.z + b.z, g_M0h[i + 2], g_M0l[i + 2]);
            split_bf16(a.w + b.w, g_M0h[i + 3], g_M0l[i + 3]);
        }
    }
    grid_sync();

    // tile mapping (R8): 8 k-splits x (2m x 8n) over [256, 1024]
    const int ksAB = bid >> 4, m0AB = ((bid >> 3) & 1) * 128, n0AB = (bid & 7) * 128;

    auto makeA = [&](int s) {
        Ph p;
        if (ksAB < 4) {
            if (s == 1) {
                p.Ah = g_yh + (long)m0AB * Ind; p.Al = g_yl + (long)m0AB * Ind;
                p.Wh = g_Wih0h + (long)n0AB * Ind; p.Wl = g_Wih0l + (long)n0AB * Ind;
                p.lda = Ind; p.ldw = Ind; p.kb = ksAB * 64; p.nch = 1; p.ready = true;
            } else {
                const long hb = (long)(s - 1) * Bm * Hd + (long)m0AB * Hd;
                p.Ah = g_H1h + hb; p.Al = g_H1l + hb;       // written by reduceB(s-1)
                p.Wh = g_M0h + (long)n0AB * Hd; p.Wl = g_M0l + (long)n0AB * Hd;
                p.lda = Hd; p.ldw = Hd; p.kb = ksAB * 256; p.nch = 4; p.ready = false;
            }
        } else {
            const int cb = (s - 1) & 1;                     // h0(s-1): stable
            p.Ah = g_h0h[cb] + (long)m0AB * Hd; p.Al = g_h0l[cb] + (long)m0AB * Hd;
            p.Wh = g_Whh0h + (long)n0AB * Hd; p.Wl = g_Whh0l + (long)n0AB * Hd;
            p.lda = Hd; p.ldw = Hd; p.kb = (ksAB - 4) * 256; p.nch = 4; p.ready = true;
        }
        return p;
    };
    auto makeB = [&](int s) {
        Ph p;
        if (ksAB < 4) {
            const int nb = s & 1;                           // h0(s): fresh after reduceA
            p.Ah = g_h0h[nb] + (long)m0AB * Hd; p.Al = g_h0l[nb] + (long)m0AB * Hd;
            p.Wh = g_Wih1h + (long)n0AB * Hd; p.Wl = g_Wih1l + (long)n0AB * Hd;
            p.lda = Hd; p.ldw = Hd; p.kb = ksAB * 256; p.nch = 4; p.ready = false;
        } else {
            const long hb = (long)(s - 1) * Bm * Hd + (long)m0AB * Hd;  // h1(s-1): stable
            p.Ah = g_H1h + hb; p.Al = g_H1l + hb;
            p.Wh = g_Whh1h + (long)n0AB * Hd; p.Wl = g_Whh1l + (long)n0AB * Hd;
            p.lda = Hd; p.ldw = Hd; p.kb = (ksAB - 4) * 256; p.nch = 4; p.ready = true;
        }
        return p;
    };

    Ph pA = makeA(1);
    prefetch_phase(sb, pA);

    for (int s = 1; s < Tt; ++s) {
        const int nb = s & 1;

        // ---- stage A: h0(s) = tanh([h1(s-1)|h0(s-1)] @ [M0|Whh0]^T + biasAf)
        start_phase(sb, pA);
        {
            float accA[4][4][4] = {};
            run_phase(accA, sb, pA);
            dump_acc(accA, g_pAB[ksAB], Hd, m0AB, n0AB);
        }
        Ph pB = makeB(s);
        prefetch_phase(sb, pB);   // W always; acts for ks>=4 (h1(s-1) stable)
        grid_sync();
        reduce_stage(s == 1 ? g_biasA1 : g_biasAf, g_h0h[nb], g_h0l[nb], gtid);
        grid_sync();

        // ---- stage B: h1(s) = tanh([h0(s)|h1(s-1)] @ [Wih1|Whh1]^T + biasB)
        start_phase(sb, pB);
        {
            float accB[4][4][4] = {};
            run_phase(accB, sb, pB);
            dump_acc(accB, g_pAB[ksAB], Hd, m0AB, n0AB);
        }
        if (s + 1 < Tt) {
            pA = makeA(s + 1);
            prefetch_phase(sb, pA);  // W always; acts for ks>=4 (h0(s) stable)
        }
        grid_sync();
        reduce_stage(g_biasB, g_H1h + (long)s * Bm * Hd, g_H1l + (long)s * Bm * Hd, gtid);
        grid_sync();
    }

    // ---- batched output GEMM: out[:, s, :] = H1[s] @ fc_W^T + fc_b, s = 1..511
    for (int job = bid; job < (Tt - 1) * 4; job += NCTA) {
        const int ntile = job & 1;
        const int rt = job >> 1;
        const int s = 1 + (rt >> 1);
        const int m0 = (rt & 1) * 128, n0 = ntile * 128;
        float acc[4][4][4] = {};
        gemm_pipe(acc, sb,
                  g_H1h + (long)s * Bm * Hd + (long)m0 * Hd,
                  g_H1l + (long)s * Bm * Hd + (long)m0 * Hd, Hd,
                  g_fcWh + (long)n0 * Hd, g_fcWl + (long)n0 * Hd, Hd,
                  0, 16);
        final_store(acc, out, fc_b, s, m0, n0);
    }
}

extern "C" void kernel_launch(void *const *d_in, const int *in_sizes, int n_in,
                              void *d_out, int out_size) {
    (void)in_sizes; (void)n_in; (void)out_size;
    const float *y0    = (const float *)d_in[0];
    // d_in[1] = t (length only; unused)
    const float *W_ih0 = (const float *)d_in[2];
    const float *W_hh0 = (const float *)d_in[3];
    const float *b_ih0 = (const float *)d_in[4];
    const float *b_hh0 = (const float *)d_in[5];
    const float *W_ih1 = (const float *)d_in[6];
    const float *W_hh1 = (const float *)d_in[7];
    const float *b_ih1 = (const float *)d_in[8];
    const float *b_hh1 = (const float *)d_in[9];
    const float *fc_W  = (const float *)d_in[10];
    const float *fc_b  = (const float *)d_in[11];
    float *out = (float *)d_out;

    cudaFuncSetAttribute(rnn_tc, cudaFuncAttributeMaxDynamicSharedMemorySize, SMEM_BYTES);
    rnn_tc<<<NCTA, NTHR, SMEM_BYTES>>>(y0, W_ih0, W_hh0, b_ih0, b_hh0,
                                       W_ih1, W_hh1, b_ih1, b_hh1,
                                       fc_W, fc_b, out);
}

// round 12
// speedup vs baseline: 1.5252x; 1.0008x over previous
#include <cuda_runtime.h>
#include <cuda_bf16.h>

// Persistent 2-layer tanh RNN, sm_103 baseline tensor cores (mma.sync bf16 x3).
// R11 = R8 (proven 15.5ms: 128 CTAs, 8-way split-K, fc folded via M0, batched
// output GEMM) + ONE change: 512 threads (16 warps, 4x4 warp grid, 32x32 warp
// tile). R8/R10 profiles show occ 12.5% (2 warps/SMSP) + issue 11% + tensor 36%
// -> HMMA/LDSM latency-bound; doubling warps/SMSP doubles latency hiding.

typedef unsigned long long u64;
typedef unsigned int u32;

namespace {
constexpr int NCTA = 128;
constexpr int NTHR = 512;
constexpr int Bm = 256, Hd = 1024, Ind = 256, Tt = 512;
// double-buffered dynamic smem: per buffer 4 bf16 tiles (Ah, Al, Wh, Wl) x 16KB
constexpr int BUFB = 65536;
constexpr int T_AH = 0, T_AL = 16384, T_WH = 32768, T_WL = 49152;
constexpr int SMEM_BYTES = 2 * BUFB;  // 128KB
}

// ---- device-global state (allocation-free rule) ----
__device__ __align__(16) __nv_bfloat16 g_Wih0h[Hd * Ind], g_Wih0l[Hd * Ind];
__device__ __align__(16) __nv_bfloat16 g_Whh0h[Hd * Hd],  g_Whh0l[Hd * Hd];
__device__ __align__(16) __nv_bfloat16 g_Wih1h[Hd * Hd],  g_Wih1l[Hd * Hd];
__device__ __align__(16) __nv_bfloat16 g_Whh1h[Hd * Hd],  g_Whh1l[Hd * Hd];
__device__ __align__(16) __nv_bfloat16 g_M0h[Hd * Hd],    g_M0l[Hd * Hd];
__device__ __align__(16) __nv_bfloat16 g_fcWh[Ind * Hd],  g_fcWl[Ind * Hd];
__device__ __align__(16) __nv_bfloat16 g_fcWTh[Hd * Ind], g_fcWTl[Hd * Ind];
__device__ __align__(16) __nv_bfloat16 g_yh[Bm * Ind],    g_yl[Bm * Ind];
__device__ __align__(16) __nv_bfloat16 g_h0h[2][Bm * Hd], g_h0l[2][Bm * Hd];
// full h1 history (hi/lo) for the batched output GEMM: 512 x 256 x 1024
__device__ __align__(16) __nv_bfloat16 g_H1h[Tt * Bm * Hd];
__device__ __align__(16) __nv_bfloat16 g_H1l[Tt * Bm * Hd];
__device__ float g_biasA1[Hd], g_biasAf[Hd], g_biasB[Hd];
__device__ float g_pAB[8][Bm * Hd];   // split-K partials (also M0 scratch: 2 x 1M)
__device__ unsigned g_arrive = 0, g_gen = 0;

// ---- helpers ----
__device__ __forceinline__ u32 smem_u32(const void *p) {
    u32 a;
    asm("{ .reg .u64 t; cvta.to.shared.u64 t, %1; cvt.u32.u64 %0, t; }"
        : "=r"(a) : "l"(p));
    return a;
}

#define LDMX4(r, a) \
    asm volatile("ldmatrix.sync.aligned.m8n8.x4.shared.b16 {%0,%1,%2,%3}, [%4];" \
                 : "=r"((r)[0]), "=r"((r)[1]), "=r"((r)[2]), "=r"((r)[3]) : "r"(a))

__device__ __forceinline__ void mma16816(float *c, const u32 *a, u32 b0, u32 b1) {
    asm volatile(
        "mma.sync.aligned.m16n8k16.row.col.f32.bf16.bf16.f32 "
        "{%0,%1,%2,%3}, {%4,%5,%6,%7}, {%8,%9}, {%0,%1,%2,%3};"
        : "+f"(c[0]), "+f"(c[1]), "+f"(c[2]), "+f"(c[3])
        : "r"(a[0]), "r"(a[1]), "r"(a[2]), "r"(a[3]), "r"(b0), "r"(b1));
}

__device__ __forceinline__ void commitg() {
    asm volatile("cp.async.commit_group;" ::: "memory");
}
__device__ __forceinline__ void waitg0() {
    asm volatile("cp.async.wait_group 0;" ::: "memory");
}
__device__ __forceinline__ void waitg1() {
    asm volatile("cp.async.wait_group 1;" ::: "memory");
}

// ---- grid barrier (validated R4-R10) ----
__device__ __forceinline__ void grid_sync() {
    __syncthreads();
    if (threadIdx.x == 0) {
        unsigned gen = *(volatile unsigned *)&g_gen;
        __threadfence();
        if (atomicAdd(&g_arrive, 1u) == NCTA - 1) {
            atomicExch(&g_arrive, 0u);
            __threadfence();
            atomicAdd(&g_gen, 1u);
        } else {
            while (*(volatile unsigned *)&g_gen == gen) { }
            __threadfence();
        }
    }
    __syncthreads();
}

__device__ __forceinline__ void split_bf16(float v, __nv_bfloat16 &h, __nv_bfloat16 &l) {
    h = __float2bfloat16(v);
    l = __float2bfloat16(v - __bfloat162float(h));
}

// cp.async one 128x64 bf16 tile (SW128 xor swizzle) into smem. 1024 x 16B copies.
__device__ __forceinline__ void stage_async(u32 sdst, const __nv_bfloat16 *g,
                                            int ld, int kb) {
    const int tid = threadIdx.x;
#pragma unroll
    for (int j = 0; j < 2; ++j) {
        const int u = tid + NTHR * j;
        const int row = u >> 3, blk = u & 7;
        const size_t src = __cvta_generic_to_global(&g[(long)row * ld + kb + blk * 8]);
        const u32 dst = sdst + row * 128 + ((blk ^ (row & 7)) << 4);
        asm volatile("cp.async.cg.shared.global [%0], [%1], 16;"
                     :: "r"(dst), "l"(src) : "memory");
    }
}

__device__ __forceinline__ void issue_chunk(
    u32 sbuf, const __nv_bfloat16 *Ah, const __nv_bfloat16 *Al, int lda,
    const __nv_bfloat16 *Wh, const __nv_bfloat16 *Wl, int ldw, int kb) {
    stage_async(sbuf + T_AH, Ah, lda, kb);
    stage_async(sbuf + T_AL, Al, lda, kb);
    stage_async(sbuf + T_WH, Wh, ldw, kb);
    stage_async(sbuf + T_WL, Wl, ldw, kb);
    commitg();
}

// MMA over one staged 64-k chunk. 16 warps as 4x4; warp tile 32x32
// (2 m-atoms x 4 n-atoms). 3 precision passes: ah*bh + ah*bl + al*bh.
__device__ __forceinline__ void mma_tile(float (&acc)[2][4][4], u32 sbase) {
    const int lid = threadIdx.x & 31, wid = threadIdx.x >> 5;
    const int wm = wid >> 2, wn = wid & 3;
    const int rA0 = wm * 32 + (lid & 7) + ((lid >> 3) & 1) * 8;
    const int cAsel = (lid >> 4) & 1;
    const int rB0 = wn * 32 + (lid & 7) + ((lid >> 4) & 1) * 8;
    const int cBsel = (lid >> 3) & 1;
#pragma unroll
    for (int k16 = 0; k16 < 4; ++k16) {
        u32 ah[2][4], al[2][4], bh[2][4], bl[2][4];
#pragma unroll
        for (int ma = 0; ma < 2; ++ma) {
            const int r = rA0 + ma * 16;
            const u32 off = (u32)(r * 128 + (((k16 * 2 + cAsel) ^ (r & 7)) << 4));
            LDMX4(ah[ma], sbase + T_AH + off);
            LDMX4(al[ma], sbase + T_AL + off);
        }
#pragma unroll
        for (int p = 0; p < 2; ++p) {
            const int r = rB0 + p * 16;
            const u32 off = (u32)(r * 128 + (((k16 * 2 + cBsel) ^ (r & 7)) << 4));
            LDMX4(bh[p], sbase + T_WH + off);
            LDMX4(bl[p], sbase + T_WL + off);
        }
#pragma unroll
        for (int ma = 0; ma < 2; ++ma)
#pragma unroll
            for (int na = 0; na < 4; ++na) {
                const int p = na >> 1, q = (na & 1) * 2;
                mma16816(acc[ma][na], ah[ma], bh[p][q], bh[p][q + 1]);
                mma16816(acc[ma][na], ah[ma], bl[p][q], bl[p][q + 1]);
                mma16816(acc[ma][na], al[ma], bh[p][q], bh[p][q + 1]);
            }
    }
}

// Double-buffered pipelined GEMM over nch 64-k chunks starting at kb (R8).
__device__ __forceinline__ void gemm_pipe(
    float (&acc)[2][4][4], u32 sb,
    const __nv_bfloat16 *Ah, const __nv_bfloat16 *Al, int lda,
    const __nv_bfloat16 *Wh, const __nv_bfloat16 *Wl, int ldw,
    int kb, int nch)
{
    issue_chunk(sb, Ah, Al, lda, Wh, Wl, ldw, kb);
    if (nch > 1) issue_chunk(sb + BUFB, Ah, Al, lda, Wh, Wl, ldw, kb + 64);
    for (int i = 0; i < nch; ++i) {
        if (i + 1 < nch) waitg1(); else waitg0();
        __syncthreads();
        mma_tile(acc, sb + (u32)((i & 1) * BUFB));
        __syncthreads();
        if (i + 2 < nch)
            issue_chunk(sb + (u32)((i & 1) * BUFB), Ah, Al, lda, Wh, Wl, ldw,
                        kb + 64 * (i + 2));
    }
}

// Dump 128x128 fp32 accumulator tile to a partial buffer.
__device__ __forceinline__ void dump_acc(
    const float (&acc)[2][4][4], float *__restrict__ dst, int ldc, int m0, int n0)
{
    const int lid = threadIdx.x & 31, wid = threadIdx.x >> 5;
    const int wm = wid >> 2, wn = wid & 3;
    const int g = lid >> 2, t = lid & 3;
#pragma unroll
    for (int ma = 0; ma < 2; ++ma)
#pragma unroll
        for (int na = 0; na < 4; ++na) {
            const int row = m0 + wm * 32 + ma * 16 + g;
            const int col = n0 + wn * 32 + na * 8 + t * 2;
            *reinterpret_cast<float2 *>(&dst[(long)row * ldc + col]) =
                make_float2(acc[ma][na][0], acc[ma][na][1]);
            *reinterpret_cast<float2 *>(&dst[(long)(row + 8) * ldc + col]) =
                make_float2(acc[ma][na][2], acc[ma][na][3]);
        }
}

// sum 8 split-K partials + bias, tanh, write bf16 hi/lo activations.
// 65536 threads x 4 elements = 256K (exact).
__device__ __forceinline__ void reduce_stage(
    const float *__restrict__ bias,
    __nv_bfloat16 *__restrict__ dh, __nv_bfloat16 *__restrict__ dl, int gtid)
{
    const int i = gtid * 4;
    const int n = i & (Hd - 1);
    float4 a = __ldcg(reinterpret_cast<const float4 *>(&g_pAB[0][i]));
#pragma unroll
    for (int p = 1; p < 8; ++p) {
        const float4 t = __ldcg(reinterpret_cast<const float4 *>(&g_pAB[p][i]));
        a.x += t.x; a.y += t.y; a.z += t.z; a.w += t.w;
    }
    const float4 vb = *reinterpret_cast<const float4 *>(&bias[n]);
    const float ox = tanhf(a.x + vb.x), oy = tanhf(a.y + vb.y);
    const float oz = tanhf(a.z + vb.z), ow = tanhf(a.w + vb.w);
    __nv_bfloat16 hx, lx, hy, ly, hz, lz, hw, lw;
    split_bf16(ox, hx, lx); split_bf16(oy, hy, ly);
    split_bf16(oz, hz, lz); split_bf16(ow, hw, lw);
    reinterpret_cast<__nv_bfloat162 *>(&dh[i])[0] = __halves2bfloat162(hx, hy);
    reinterpret_cast<__nv_bfloat162 *>(&dh[i])[1] = __halves2bfloat162(hz, hw);
    reinterpret_cast<__nv_bfloat162 *>(&dl[i])[0] = __halves2bfloat162(lx, ly);
    reinterpret_cast<__nv_bfloat162 *>(&dl[i])[1] = __halves2bfloat162(lz, lw);
}

__device__ __forceinline__ void convert_split(
    const float *__restrict__ s, __nv_bfloat16 *dh, __nv_bfloat16 *dl, int n, int gtid)
{
    for (int i = gtid; i < n; i += NCTA * NTHR) split_bf16(s[i], dh[i], dl[i]);
}

// Final-GEMM epilogue: out[:, s, :] tile = acc + fc_b
__device__ __forceinline__ void final_store(
    const float (&acc)[2][4][4], float *__restrict__ out,
    const float *__restrict__ fc_b, int s, int m0, int n0)
{
    const int lid = threadIdx.x & 31, wid = threadIdx.x >> 5;
    const int wm = wid >> 2, wn = wid & 3;
    const int g = lid >> 2, t = lid & 3;
#pragma unroll
    for (int ma = 0; ma < 2; ++ma)
#pragma unroll
        for (int na = 0; na < 4; ++na) {
            const int row = m0 + wm * 32 + ma * 16 + g;
            const int col = n0 + wn * 32 + na * 8 + t * 2;
            const float bx = fc_b[col], by = fc_b[col + 1];
            *reinterpret_cast<float2 *>(
                &out[(long)row * (Tt * Ind) + (long)s * Ind + col]) =
                make_float2(acc[ma][na][0] + bx, acc[ma][na][1] + by);
            *reinterpret_cast<float2 *>(
                &out[(long)(row + 8) * (Tt * Ind) + (long)s * Ind + col]) =
                make_float2(acc[ma][na][2] + bx, acc[ma][na][3] + by);
        }
}

__global__ void __launch_bounds__(NTHR, 1) rnn_tc(
    const float *__restrict__ y0,
    const float *__restrict__ W_ih0, const float *__restrict__ W_hh0,
    const float *__restrict__ b_ih0, const float *__restrict__ b_hh0,
    const float *__restrict__ W_ih1, const float *__restrict__ W_hh1,
    const float *__restrict__ b_ih1, const float *__restrict__ b_hh1,
    const float *__restrict__ fc_W, const float *__restrict__ fc_b,
    float *__restrict__ out)
{
    extern __shared__ char smem[];
    const u32 sb = smem_u32(smem);
    const int tid = threadIdx.x, bid = blockIdx.x;
    const int gtid = bid * NTHR + tid;
    const int stride = NCTA * NTHR;

    // ---- phase 0a (every replay): splits, transpose, init, biases
    convert_split(W_ih0, g_Wih0h, g_Wih0l, Hd * Ind, gtid);
    convert_split(W_hh0, g_Whh0h, g_Whh0l, Hd * Hd, gtid);
    convert_split(W_ih1, g_Wih1h, g_Wih1l, Hd * Hd, gtid);
    convert_split(W_hh1, g_Whh1h, g_Whh1l, Hd * Hd, gtid);
    convert_split(fc_W, g_fcWh, g_fcWl, Ind * Hd, gtid);
    for (int i = gtid; i < Hd * Ind; i += stride) {  // fcWT[j][k] = fc_W[k][j]
        const int j = i >> 8, k = i & 255;
        split_bf16(fc_W[(long)k * Hd + j], g_fcWTh[i], g_fcWTl[i]);
    }
    for (int i = gtid; i < Bm * Ind; i += stride) {
        const float v = y0[i];
        split_bf16(v, g_yh[i], g_yl[i]);
        out[(long)(i >> 8) * (Tt * Ind) + (i & 255)] = v;  // out[:, 0, :]
    }
    for (int i = gtid; i < Bm * Hd; i += stride) {
        const __nv_bfloat16 z = __float2bfloat16(0.0f);
        g_h0h[0][i] = z; g_h0l[0][i] = z;
        g_H1h[i] = z;    g_H1l[i] = z;   // history slot 0 = h1 initial state
    }
    for (int j = gtid; j < Hd; j += stride) {
        const float s1 = b_ih0[j] + b_hh0[j];
        g_biasA1[j] = s1;
        float a = 0.0f;
        const float *wr = &W_ih0[(long)j * Ind];
        for (int k = 0; k < Ind; ++k) a += wr[k] * fc_b[k];
        g_biasAf[j] = a + s1;              // (fc_b @ W_ih0^T + b_ih0 + b_hh0)
        g_biasB[j] = b_ih1[j] + b_hh1[j];
    }
    grid_sync();

    // ---- phase 0b: M0 = W_ih0 @ fc_W  (1024x1024, K=256), 64 tiles x 2 k-splits
    {
        const int ks = bid >> 6, tj = bid & 63, tm = tj >> 3, tn = tj & 7;
        float acc[2][4][4] = {};
        gemm_pipe(acc, sb,
                  g_Wih0h + (long)tm * 128 * Ind, g_Wih0l + (long)tm * 128 * Ind, Ind,
                  g_fcWTh + (long)tn * 128 * Ind, g_fcWTl + (long)tn * 128 * Ind, Ind,
                  ks * 128, 2);
        dump_acc(acc, &g_pAB[0][0] + (long)ks * Hd * Hd, Hd, tm * 128, tn * 128);
    }
    grid_sync();
    {   // M0 reduce + split to bf16 hi/lo
        const float *p0 = &g_pAB[0][0];
        const float *p1 = p0 + (long)Hd * Hd;
        for (int i = gtid * 4; i < Hd * Hd; i += stride * 4) {
            const float4 a = __ldcg(reinterpret_cast<const float4 *>(&p0[i]));
            const float4 b = __ldcg(reinterpret_cast<const float4 *>(&p1[i]));
            split_bf16(a.x + b.x, g_M0h[i], g_M0l[i]);
            split_bf16(a.y + b.y, g_M0h[i + 1], g_M0l[i + 1]);
            split_bf16(a.z + b.z, g_M0h[i + 2], g_M0l[i + 2]);
            split_bf16(a.w + b.w, g_M0h[i + 3], g_M0l[i + 3]);
        }
    }
    grid_sync();

    // tile mapping: 8 k-splits x (2m x 8n) over [256, 1024]
    const int ksAB = bid >> 4, m0AB = ((bid >> 3) & 1) * 128, n0AB = (bid & 7) * 128;

    for (int s = 1; s < Tt; ++s) {
        const int cb = (s - 1) & 1, nb = s & 1;
        const __nv_bfloat16 *h1ph = g_H1h + (long)(s - 1) * Bm * Hd;
        const __nv_bfloat16 *h1pl = g_H1l + (long)(s - 1) * Bm * Hd;

        // ---- stage A: [h1prev | h0c] @ [M0 | W_hh0]^T  (K=2048; s==1: y0 @ W_ih0^T)
        {
            float acc[2][4][4] = {};
            if (ksAB < 4) {
                if (s == 1)
                    gemm_pipe(acc, sb,
                              g_yh + (long)m0AB * Ind, g_yl + (long)m0AB * Ind, Ind,
                              g_Wih0h + (long)n0AB * Ind, g_Wih0l + (long)n0AB * Ind, Ind,
                              ksAB * 64, 1);
                else
                    gemm_pipe(acc, sb,
                              h1ph + (long)m0AB * Hd, h1pl + (long)m0AB * Hd, Hd,
                              g_M0h + (long)n0AB * Hd, g_M0l + (long)n0AB * Hd, Hd,
                              ksAB * 256, 4);
            } else {
                gemm_pipe(acc, sb,
                          g_h0h[cb] + (long)m0AB * Hd, g_h0l[cb] + (long)m0AB * Hd, Hd,
                          g_Whh0h + (long)n0AB * Hd, g_Whh0l + (long)n0AB * Hd, Hd,
                          (ksAB - 4) * 256, 4);
            }
            dump_acc(acc, g_pAB[ksAB], Hd, m0AB, n0AB);
        }
        grid_sync();
        reduce_stage(s == 1 ? g_biasA1 : g_biasAf, g_h0h[nb], g_h0l[nb], gtid);
        grid_sync();

        // ---- stage B: [h0n | h1prev] @ [W_ih1 | W_hh1]^T  (K=2048)
        {
            float acc[2][4][4] = {};
            if (ksAB < 4)
                gemm_pipe(acc, sb,
                          g_h0h[nb] + (long)m0AB * Hd, g_h0l[nb] + (long)m0AB * Hd, Hd,
                          g_Wih1h + (long)n0AB * Hd, g_Wih1l + (long)n0AB * Hd, Hd,
                          ksAB * 256, 4);
            else
                gemm_pipe(acc, sb,
                          h1ph + (long)m0AB * Hd, h1pl + (long)m0AB * Hd, Hd,
                          g_Whh1h + (long)n0AB * Hd, g_Whh1l + (long)n0AB * Hd, Hd,
                          (ksAB - 4) * 256, 4);
            dump_acc(acc, g_pAB[ksAB], Hd, m0AB, n0AB);
        }
        grid_sync();
        reduce_stage(g_biasB, g_H1h + (long)s * Bm * Hd, g_H1l + (long)s * Bm * Hd, gtid);
        grid_sync();
    }

    // ---- batched output GEMM: out[:, s, :] = H1[s] @ fc_W^T + fc_b, s = 1..511
    for (int job = bid; job < (Tt - 1) * 4; job += NCTA) {
        const int ntile = job & 1;
        const int rt = job >> 1;
        const int s = 1 + (rt >> 1);
        const int m0 = (rt & 1) * 128, n0 = ntile * 128;
        float acc[2][4][4] = {};
        gemm_pipe(acc, sb,
                  g_H1h + (long)s * Bm * Hd + (long)m0 * Hd,
                  g_H1l + (long)s * Bm * Hd + (long)m0 * Hd, Hd,
                  g_fcWh + (long)n0 * Hd, g_fcWl + (long)n0 * Hd, Hd,
                  0, 16);
        final_store(acc, out, fc_b, s, m0, n0);
    }
}

extern "C" void kernel_launch(void *const *d_in, const int *in_sizes, int n_in,
                              void *d_out, int out_size) {
    (void)in_sizes; (void)n_in; (void)out_size;
    const float *y0    = (const float *)d_in[0];
    // d_in[1] = t (length only; unused)
    const float *W_ih0 = (const float *)d_in[2];
    const float *W_hh0 = (const float *)d_in[3];
    const float *b_ih0 = (const float *)d_in[4];
    const float *b_hh0 = (const float *)d_in[5];
    const float *W_ih1 = (const float *)d_in[6];
    const float *W_hh1 = (const float *)d_in[7];
    const float *b_ih1 = (const float *)d_in[8];
    const float *b_hh1 = (const float *)d_in[9];
    const float *fc_W  = (const float *)d_in[10];
    const float *fc_b  = (const float *)d_in[11];
    float *out = (float *)d_out;

    cudaFuncSetAttribute(rnn_tc, cudaFuncAttributeMaxDynamicSharedMemorySize, SMEM_BYTES);
    rnn_tc<<<NCTA, NTHR, SMEM_BYTES>>>(y0, W_ih0, W_hh0, b_ih0, b_hh0,
                                       W_ih1, W_hh1, b_ih1, b_hh1,
                                       fc_W, fc_b, out);
}